// round 8
// baseline (speedup 1.0000x reference)
#include <cuda_runtime.h>

// VariationalGCNEncoder: N=100000, E=1600000, IN=256, HID=128, OUT=64
#define NN   100000
#define EMAX 1700000
#define INF  256
#define HID  128
#define OUTF 64
#define EPSV 1e-5f

// ---------------- scratch (device globals; no runtime allocation) ----------------
__device__ float g_dinv[NN];                     // rsqrt(1 + in-degree)
__device__ float g_XW [(size_t)NN * 128];        // XWs = (A@W)*dinv[row]  (pre-scaled)
__device__ float g_AGG[(size_t)NN * 128];        // aggregation result
__device__ float g_stats[2][256];                // per-layer [sum(128)|sumsq(128)]
__device__ float g_coef [2][256];                // per-layer [scale(128)|shift(128)]
__device__ int   g_cnt   [NN];                   // in-degree histogram
__device__ int   g_rows  [NN + 1];               // CSR row starts
__device__ int   g_cursor[NN];                   // fill cursors for reorder
__device__ int   g_part  [512];                  // scan partials
__device__ int   g_esrc  [EMAX];                 // edge sources, grouped by dst

// ---------------- init: zero degree histogram + BN stats ----------------
__global__ void k_init(int n) {
    int i = blockIdx.x * blockDim.x + threadIdx.x;
    if (i < n) g_cnt[i] = 0;
    if (i < 512) ((float*)g_stats)[i] = 0.0f;
}

__global__ void k_deg(const int* __restrict__ dst, int e) {
    int i = blockIdx.x * blockDim.x + threadIdx.x;
    if (i < e) atomicAdd(&g_cnt[dst[i]], 1);
}

// ---------------- CSR build: 3-stage exclusive scan + reorder ----------------
__global__ void k_scan_a(int n) {                 // per-block partial sums
    __shared__ int sh[256];
    int i = blockIdx.x * 256 + threadIdx.x;
    sh[threadIdx.x] = (i < n) ? g_cnt[i] : 0;
    __syncthreads();
    for (int s = 128; s > 0; s >>= 1) {
        if (threadIdx.x < s) sh[threadIdx.x] += sh[threadIdx.x + s];
        __syncthreads();
    }
    if (threadIdx.x == 0) g_part[blockIdx.x] = sh[0];
}

__global__ void k_scan_b(int nb, int n, int e) {  // exclusive scan of partials (1 block, 512 thr)
    __shared__ int sh[512];
    int t = threadIdx.x;
    sh[t] = (t < nb) ? g_part[t] : 0;
    __syncthreads();
    for (int off = 1; off < 512; off <<= 1) {     // Hillis-Steele inclusive
        int add = (t >= off) ? sh[t - off] : 0;
        __syncthreads();
        sh[t] += add;
        __syncthreads();
    }
    if (t < nb) g_part[t] = (t == 0) ? 0 : sh[t - 1];
    if (t == 0) g_rows[n] = e;
}

__global__ void k_scan_c(int n) {                 // per-block exclusive scan + finalize
    __shared__ int sh[256];
    int i = blockIdx.x * 256 + threadIdx.x;
    int v = (i < n) ? g_cnt[i] : 0;
    sh[threadIdx.x] = v;
    __syncthreads();
    for (int off = 1; off < 256; off <<= 1) {
        int add = (threadIdx.x >= off) ? sh[threadIdx.x - off] : 0;
        __syncthreads();
        sh[threadIdx.x] += add;
        __syncthreads();
    }
    if (i < n) {
        int r = sh[threadIdx.x] - v + g_part[blockIdx.x];   // exclusive prefix
        g_rows[i]   = r;
        g_cursor[i] = r;
        g_dinv[i]   = rsqrtf((float)(v + 1));               // +1 self-loop
    }
}

__global__ void k_reorder(const int* __restrict__ src, const int* __restrict__ dst, int e) {
    int i = blockIdx.x * blockDim.x + threadIdx.x;
    if (i < e) {
        int pos = atomicAdd(&g_cursor[dst[i]], 1);
        g_esrc[pos] = src[i];
    }
}

// ---------------- SGEMM + fused pre-BN-ReLU (A side) + norm epilogue -------------
// C-tile 128x128, K-step 16, double-buffered smem, 256 threads, 8x8 micro-tile.
// BNA=false: A from param pointer. BNA=true: A = relu(g_AGG*scale+shift).
// Epilogue: g_XW[row] = acc * dinv[row]  (symmetric-norm pre-scale).
template <int K, bool BNA>
__global__ void __launch_bounds__(256) k_gemm(const float* __restrict__ A,
                                              const float* __restrict__ B1,
                                              const float* __restrict__ B2,
                                              int NC1, int cw, int nrows) {
    __shared__ float As[2][16][132];
    __shared__ float Bs[2][16][128];

    const int t  = threadIdx.x;
    const int tx = t & 15;
    const int ty = t >> 4;
    const int r0 = blockIdx.x * 128;

    float acc[8][8];
#pragma unroll
    for (int i = 0; i < 8; i++)
#pragma unroll
        for (int j = 0; j < 8; j++) acc[i][j] = 0.0f;

    const int lrow  = t >> 1;
    const int lkq   = (t & 1) * 8;
    const int grow  = r0 + lrow;
    const bool rowok = (grow < nrows);
    const int bkr = t >> 4;
    const int bc  = (t & 15) * 8;
    const float* cf = g_coef[cw];
    const float* Bp;
    int bstr;
    if (bc < NC1) { Bp = B1 + bc;          bstr = NC1; }
    else          { Bp = B2 + (bc - NC1);  bstr = 128 - NC1; }

    float4 a0, a1, b0, b1;

    auto load_tile = [&](int k0) {
        a0 = make_float4(0.f, 0.f, 0.f, 0.f);
        a1 = make_float4(0.f, 0.f, 0.f, 0.f);
        if (rowok) {
            int kc = k0 + lkq;
            if (BNA) {
                float4 v0 = *(const float4*)(g_AGG + (size_t)grow * 128 + kc);
                float4 v1 = *(const float4*)(g_AGG + (size_t)grow * 128 + kc + 4);
                a0.x = fmaxf(fmaf(v0.x, cf[kc + 0], cf[128 + kc + 0]), 0.f);
                a0.y = fmaxf(fmaf(v0.y, cf[kc + 1], cf[128 + kc + 1]), 0.f);
                a0.z = fmaxf(fmaf(v0.z, cf[kc + 2], cf[128 + kc + 2]), 0.f);
                a0.w = fmaxf(fmaf(v0.w, cf[kc + 3], cf[128 + kc + 3]), 0.f);
                a1.x = fmaxf(fmaf(v1.x, cf[kc + 4], cf[128 + kc + 4]), 0.f);
                a1.y = fmaxf(fmaf(v1.y, cf[kc + 5], cf[128 + kc + 5]), 0.f);
                a1.z = fmaxf(fmaf(v1.z, cf[kc + 6], cf[128 + kc + 6]), 0.f);
                a1.w = fmaxf(fmaf(v1.w, cf[kc + 7], cf[128 + kc + 7]), 0.f);
            } else {
                a0 = *(const float4*)(A + (size_t)grow * K + kc);
                a1 = *(const float4*)(A + (size_t)grow * K + kc + 4);
            }
        }
        size_t brow = (size_t)(k0 + bkr) * bstr;
        b0 = *(const float4*)(Bp + brow);
        b1 = *(const float4*)(Bp + brow + 4);
    };

    auto store_tile = [&](int buf) {
        As[buf][lkq + 0][lrow] = a0.x;
        As[buf][lkq + 1][lrow] = a0.y;
        As[buf][lkq + 2][lrow] = a0.z;
        As[buf][lkq + 3][lrow] = a0.w;
        As[buf][lkq + 4][lrow] = a1.x;
        As[buf][lkq + 5][lrow] = a1.y;
        As[buf][lkq + 6][lrow] = a1.z;
        As[buf][lkq + 7][lrow] = a1.w;
        *(float4*)&Bs[buf][bkr][bc]     = b0;
        *(float4*)&Bs[buf][bkr][bc + 4] = b1;
    };

    auto compute = [&](int buf) {
#pragma unroll
        for (int kk = 0; kk < 16; kk++) {
            float4 ra0 = *(const float4*)&As[buf][kk][ty * 8];
            float4 ra1 = *(const float4*)&As[buf][kk][ty * 8 + 4];
            float4 rb0 = *(const float4*)&Bs[buf][kk][tx * 8];
            float4 rb1 = *(const float4*)&Bs[buf][kk][tx * 8 + 4];
            float a[8] = {ra0.x, ra0.y, ra0.z, ra0.w, ra1.x, ra1.y, ra1.z, ra1.w};
            float b[8] = {rb0.x, rb0.y, rb0.z, rb0.w, rb1.x, rb1.y, rb1.z, rb1.w};
#pragma unroll
            for (int i = 0; i < 8; i++)
#pragma unroll
                for (int j = 0; j < 8; j++) acc[i][j] += a[i] * b[j];
        }
    };

    load_tile(0);
    store_tile(0);
    __syncthreads();
    int buf = 0;
    for (int k0 = 16; k0 < K; k0 += 16) {
        load_tile(k0);
        compute(buf);
        store_tile(buf ^ 1);
        __syncthreads();
        buf ^= 1;
    }
    compute(buf);

#pragma unroll
    for (int i = 0; i < 8; i++) {
        int gr = r0 + ty * 8 + i;
        if (gr < nrows) {
            float d  = g_dinv[gr];
            size_t base = (size_t)gr * 128 + tx * 8;
            float4 o0 = make_float4(acc[i][0] * d, acc[i][1] * d, acc[i][2] * d, acc[i][3] * d);
            float4 o1 = make_float4(acc[i][4] * d, acc[i][5] * d, acc[i][6] * d, acc[i][7] * d);
            *(float4*)(g_XW + base)     = o0;
            *(float4*)(g_XW + base + 4) = o1;
        }
    }
}

// ---------------- CSR aggregation: one warp per node, zero atomics ----------------
// AGG[d] = (XWs[d] + sum_{incoming} XWs[src]) * dinv[d]
// MODE 0: write g_AGG + fused BN column stats (block-reduced, atomics to g_stats[which]).
// MODE 1: head — apply bmu/bls and write split mu/logstd directly to out.
// 512 threads = 16 warps/block (halves block count + stats atomic traffic vs 256).
template <int MODE>
__global__ void __launch_bounds__(512) k_agg(int n, int which,
                                             const float* __restrict__ bmu,
                                             const float* __restrict__ bls,
                                             float* __restrict__ out) {
    const int gid  = blockIdx.x * blockDim.x + threadIdx.x;
    const int node = gid >> 5;
    const int lane = gid & 31;
    const bool ok  = (node < n);

    float4 o = make_float4(0.f, 0.f, 0.f, 0.f);
    if (ok) {
        const int base = __ldg(&g_rows[node]);
        const int end  = __ldg(&g_rows[node + 1]);
        const size_t loff = (size_t)lane * 4;

        float4 acc = __ldg((const float4*)(g_XW + (size_t)node * 128 + loff));  // self-loop
        float4 acc2 = make_float4(0.f, 0.f, 0.f, 0.f);

        int j = base;
        for (; j + 3 < end; j += 4) {             // 4-way unroll: MLP_eff ~4 on the gather chain
            int s0 = __ldg(&g_esrc[j]);
            int s1 = __ldg(&g_esrc[j + 1]);
            int s2 = __ldg(&g_esrc[j + 2]);
            int s3 = __ldg(&g_esrc[j + 3]);
            float4 v0 = __ldg((const float4*)(g_XW + (size_t)s0 * 128 + loff));
            float4 v1 = __ldg((const float4*)(g_XW + (size_t)s1 * 128 + loff));
            float4 v2 = __ldg((const float4*)(g_XW + (size_t)s2 * 128 + loff));
            float4 v3 = __ldg((const float4*)(g_XW + (size_t)s3 * 128 + loff));
            acc.x  += v0.x + v1.x;  acc.y  += v0.y + v1.y;
            acc.z  += v0.z + v1.z;  acc.w  += v0.w + v1.w;
            acc2.x += v2.x + v3.x;  acc2.y += v2.y + v3.y;
            acc2.z += v2.z + v3.z;  acc2.w += v2.w + v3.w;
        }
        for (; j < end; j++) {
            int s0 = __ldg(&g_esrc[j]);
            float4 v0 = __ldg((const float4*)(g_XW + (size_t)s0 * 128 + loff));
            acc.x += v0.x; acc.y += v0.y; acc.z += v0.z; acc.w += v0.w;
        }
        acc.x += acc2.x; acc.y += acc2.y; acc.z += acc2.z; acc.w += acc2.w;

        float w = __ldg(&g_dinv[node]);
        o = make_float4(acc.x * w, acc.y * w, acc.z * w, acc.w * w);

        if (MODE == 0) {
            *(float4*)(g_AGG + (size_t)node * 128 + (size_t)lane * 4) = o;
        } else {
            if (lane < 16) {
                int c = lane * 4;
                float4 r = make_float4(o.x + bmu[c], o.y + bmu[c + 1],
                                       o.z + bmu[c + 2], o.w + bmu[c + 3]);
                *(float4*)(out + (size_t)node * 64 + c) = r;
            } else {
                int c = (lane - 16) * 4;
                float4 r = make_float4(o.x + bls[c], o.y + bls[c + 1],
                                       o.z + bls[c + 2], o.w + bls[c + 3]);
                *(float4*)(out + (size_t)n * 64 + (size_t)node * 64 + c) = r;
            }
        }
    }

    if (MODE == 0) {
        // fused BN stats: block-reduce 16 warps' rows, then 256 atomics to g_stats[which].
        // Tail warps (node >= n) contribute zeros (stats-neutral). No early returns above.
        __shared__ float ssum[16][128];
        __shared__ float ssq [16][128];
        const int w16 = threadIdx.x >> 5;
        *(float4*)&ssum[w16][lane * 4] = o;
        float4 q = make_float4(o.x * o.x, o.y * o.y, o.z * o.z, o.w * o.w);
        *(float4*)&ssq[w16][lane * 4] = q;
        __syncthreads();

        if (w16 == 0) {
#pragma unroll
            for (int j = 0; j < 4; j++) {
                int c = lane * 4 + j;
                float s = 0.f, sq = 0.f;
#pragma unroll
                for (int r = 0; r < 16; r++) { s += ssum[r][c]; sq += ssq[r][c]; }
                atomicAdd(&g_stats[which][c],       s);
                atomicAdd(&g_stats[which][128 + c], sq);
            }
        }
    }
}

__global__ void k_coef(int which, const float* __restrict__ g,
                       const float* __restrict__ bt, float invn) {
    int c = threadIdx.x;  // 128 threads
    float m  = g_stats[which][c] * invn;
    float vv = g_stats[which][128 + c] * invn - m * m;
    float sc = g[c] * rsqrtf(vv + EPSV);
    g_coef[which][c]       = sc;
    g_coef[which][128 + c] = bt[c] - m * sc;   // conv bias cancels under BN mean-subtraction
}

// ---------------- launch ----------------
extern "C" void kernel_launch(void* const* d_in, const int* in_sizes, int n_in,
                              void* d_out, int out_size) {
    const float* x   = (const float*)d_in[0];
    const float* W1  = (const float*)d_in[1];
    const float* g1  = (const float*)d_in[3];
    const float* bt1 = (const float*)d_in[4];
    const float* W2  = (const float*)d_in[5];
    const float* g2  = (const float*)d_in[7];
    const float* bt2 = (const float*)d_in[8];
    const float* Wmu = (const float*)d_in[9];
    const float* bmu = (const float*)d_in[10];
    const float* Wls = (const float*)d_in[11];
    const float* bls = (const float*)d_in[12];
    const int*   ei  = (const int*)d_in[13];
    float* out = (float*)d_out;

    const int n = in_sizes[0] / INF;      // 100000
    const int e = in_sizes[13] / 2;       // 1600000
    const int* src = ei;
    const int* dst = ei + e;

    const int TB = 256;
    const int nb_n    = (n + TB - 1) / TB;            // 391
    const int nb_e    = (e + TB - 1) / TB;
    const int nb_agg  = (n * 32 + 511) / 512;         // 16 warps/block, 1 warp/node
    const int nb_gemm = (n + 127) / 128;
    const float invn = 1.0f / (float)n;

    // degree histogram -> CSR by dst (rebuilt every replay; deterministic)
    k_init<<<nb_n, TB>>>(n);
    k_deg<<<nb_e, TB>>>(dst, e);
    k_scan_a<<<nb_n, TB>>>(n);
    k_scan_b<<<1, 512>>>(nb_n, n, e);
    k_scan_c<<<nb_n, TB>>>(n);
    k_reorder<<<nb_e, TB>>>(src, dst, e);

    // ---- layer 1: conv(x,W1) -> CSR aggregate [stats fused] -> BN coefs ----
    k_gemm<INF, false><<<nb_gemm, TB>>>(x, W1, W1, 128, 0, n);
    k_agg<0><<<nb_agg, 512>>>(n, 0, nullptr, nullptr, nullptr);
    k_coef<<<1, 128>>>(0, g1, bt1, invn);

    // ---- layer 2: conv(relu(bn(AGG)),W2) [BN fused into A-load] ----
    k_gemm<HID, true><<<nb_gemm, TB>>>(nullptr, W2, W2, 128, 0, n);
    k_agg<0><<<nb_agg, 512>>>(n, 1, nullptr, nullptr, nullptr);
    k_coef<<<1, 128>>>(1, g2, bt2, invn);

    // ---- heads: conv(relu(bn(AGG)), [Wmu|Wls]) -> aggregate + biases -> out ----
    k_gemm<HID, true><<<nb_gemm, TB>>>(nullptr, Wmu, Wls, OUTF, 1, n);
    k_agg<1><<<nb_agg, 512>>>(n, 0, bmu, bls, out);
}

// round 15
// speedup vs baseline: 1.0009x; 1.0009x over previous
#include <cuda_runtime.h>

// VariationalGCNEncoder: N=100000, E=1600000, IN=256, HID=128, OUT=64
#define NN   100000
#define EMAX 1700000
#define INF  256
#define HID  128
#define OUTF 64
#define EPSV 1e-5f

// ---------------- scratch (device globals; no runtime allocation) ----------------
__device__ float g_dinv[NN];                     // rsqrt(1 + in-degree)
__device__ float g_XW [(size_t)NN * 128];        // XWs = (A@W)*dinv[row]  (pre-scaled)
__device__ float g_AGG[(size_t)NN * 128];        // aggregation result
__device__ float g_stats[2][256];                // per-layer [sum(128)|sumsq(128)]
__device__ float g_coef [2][256];                // per-layer [scale(128)|shift(128)]
__device__ int   g_cnt   [NN];                   // in-degree histogram
__device__ int   g_rows  [NN + 1];               // CSR row starts
__device__ int   g_cursor[NN];                   // fill cursors for reorder
__device__ int   g_part  [512];                  // scan partials
__device__ int   g_esrc  [EMAX];                 // edge sources, grouped by dst

// ---------------- init: zero degree histogram + BN stats ----------------
__global__ void k_init(int n) {
    int i = blockIdx.x * blockDim.x + threadIdx.x;
    if (i < n) g_cnt[i] = 0;
    if (i < 512) ((float*)g_stats)[i] = 0.0f;
}

__global__ void k_deg(const int* __restrict__ dst, int e) {
    int i = blockIdx.x * blockDim.x + threadIdx.x;
    if (i < e) atomicAdd(&g_cnt[dst[i]], 1);
}

// ---------------- CSR build: 3-stage exclusive scan + reorder ----------------
__global__ void k_scan_a(int n) {                 // per-block partial sums
    __shared__ int sh[256];
    int i = blockIdx.x * 256 + threadIdx.x;
    sh[threadIdx.x] = (i < n) ? g_cnt[i] : 0;
    __syncthreads();
    for (int s = 128; s > 0; s >>= 1) {
        if (threadIdx.x < s) sh[threadIdx.x] += sh[threadIdx.x + s];
        __syncthreads();
    }
    if (threadIdx.x == 0) g_part[blockIdx.x] = sh[0];
}

__global__ void k_scan_b(int nb, int n, int e) {  // exclusive scan of partials (1 block, 512 thr)
    __shared__ int sh[512];
    int t = threadIdx.x;
    sh[t] = (t < nb) ? g_part[t] : 0;
    __syncthreads();
    for (int off = 1; off < 512; off <<= 1) {     // Hillis-Steele inclusive
        int add = (t >= off) ? sh[t - off] : 0;
        __syncthreads();
        sh[t] += add;
        __syncthreads();
    }
    if (t < nb) g_part[t] = (t == 0) ? 0 : sh[t - 1];
    if (t == 0) g_rows[n] = e;
}

__global__ void k_scan_c(int n) {                 // per-block exclusive scan + finalize
    __shared__ int sh[256];
    int i = blockIdx.x * 256 + threadIdx.x;
    int v = (i < n) ? g_cnt[i] : 0;
    sh[threadIdx.x] = v;
    __syncthreads();
    for (int off = 1; off < 256; off <<= 1) {
        int add = (threadIdx.x >= off) ? sh[threadIdx.x - off] : 0;
        __syncthreads();
        sh[threadIdx.x] += add;
        __syncthreads();
    }
    if (i < n) {
        int r = sh[threadIdx.x] - v + g_part[blockIdx.x];   // exclusive prefix
        g_rows[i]   = r;
        g_cursor[i] = r;
        g_dinv[i]   = rsqrtf((float)(v + 1));               // +1 self-loop
    }
}

__global__ void k_reorder(const int* __restrict__ src, const int* __restrict__ dst, int e) {
    int i = blockIdx.x * blockDim.x + threadIdx.x;
    if (i < e) {
        int pos = atomicAdd(&g_cursor[dst[i]], 1);
        g_esrc[pos] = src[i];
    }
}

// ---------------- SGEMM + fused pre-BN-ReLU (A side) + norm epilogue -------------
// C-tile 128x128, K-step 16, double-buffered smem, 256 threads, 8x8 micro-tile.
// Inner loop uses packed fma.rn.f32x2 (FFMA2): 32 FMA2 + 8 packs per kk vs 64 FFMA.
// BNA=false: A from param pointer. BNA=true: A = relu(g_AGG*scale+shift).
// Epilogue: g_XW[row] = acc * dinv[row]  (symmetric-norm pre-scale).
template <int K, bool BNA>
__global__ void __launch_bounds__(256) k_gemm(const float* __restrict__ A,
                                              const float* __restrict__ B1,
                                              const float* __restrict__ B2,
                                              int NC1, int cw, int nrows) {
    __shared__ float As[2][16][132];
    __shared__ float Bs[2][16][128];

    const int t  = threadIdx.x;
    const int tx = t & 15;
    const int ty = t >> 4;
    const int r0 = blockIdx.x * 128;

    // packed accumulators: acc2[i][jp] holds C columns (tx*8+2jp, tx*8+2jp+1)
    unsigned long long acc2[8][4];
#pragma unroll
    for (int i = 0; i < 8; i++)
#pragma unroll
        for (int jp = 0; jp < 4; jp++) acc2[i][jp] = 0ull;

    const int lrow  = t >> 1;
    const int lkq   = (t & 1) * 8;
    const int grow  = r0 + lrow;
    const bool rowok = (grow < nrows);
    const int bkr = t >> 4;
    const int bc  = (t & 15) * 8;
    const float* cf = g_coef[cw];
    const float* Bp;
    int bstr;
    if (bc < NC1) { Bp = B1 + bc;          bstr = NC1; }
    else          { Bp = B2 + (bc - NC1);  bstr = 128 - NC1; }

    float4 a0, a1, b0, b1;

    auto load_tile = [&](int k0) {
        a0 = make_float4(0.f, 0.f, 0.f, 0.f);
        a1 = make_float4(0.f, 0.f, 0.f, 0.f);
        if (rowok) {
            int kc = k0 + lkq;
            if (BNA) {
                float4 v0 = *(const float4*)(g_AGG + (size_t)grow * 128 + kc);
                float4 v1 = *(const float4*)(g_AGG + (size_t)grow * 128 + kc + 4);
                a0.x = fmaxf(fmaf(v0.x, cf[kc + 0], cf[128 + kc + 0]), 0.f);
                a0.y = fmaxf(fmaf(v0.y, cf[kc + 1], cf[128 + kc + 1]), 0.f);
                a0.z = fmaxf(fmaf(v0.z, cf[kc + 2], cf[128 + kc + 2]), 0.f);
                a0.w = fmaxf(fmaf(v0.w, cf[kc + 3], cf[128 + kc + 3]), 0.f);
                a1.x = fmaxf(fmaf(v1.x, cf[kc + 4], cf[128 + kc + 4]), 0.f);
                a1.y = fmaxf(fmaf(v1.y, cf[kc + 5], cf[128 + kc + 5]), 0.f);
                a1.z = fmaxf(fmaf(v1.z, cf[kc + 6], cf[128 + kc + 6]), 0.f);
                a1.w = fmaxf(fmaf(v1.w, cf[kc + 7], cf[128 + kc + 7]), 0.f);
            } else {
                a0 = *(const float4*)(A + (size_t)grow * K + kc);
                a1 = *(const float4*)(A + (size_t)grow * K + kc + 4);
            }
        }
        size_t brow = (size_t)(k0 + bkr) * bstr;
        b0 = *(const float4*)(Bp + brow);
        b1 = *(const float4*)(Bp + brow + 4);
    };

    auto store_tile = [&](int buf) {
        As[buf][lkq + 0][lrow] = a0.x;
        As[buf][lkq + 1][lrow] = a0.y;
        As[buf][lkq + 2][lrow] = a0.z;
        As[buf][lkq + 3][lrow] = a0.w;
        As[buf][lkq + 4][lrow] = a1.x;
        As[buf][lkq + 5][lrow] = a1.y;
        As[buf][lkq + 6][lrow] = a1.z;
        As[buf][lkq + 7][lrow] = a1.w;
        *(float4*)&Bs[buf][bkr][bc]     = b0;
        *(float4*)&Bs[buf][bkr][bc + 4] = b1;
    };

    auto compute = [&](int buf) {
#pragma unroll
        for (int kk = 0; kk < 16; kk++) {
            float4 ra0 = *(const float4*)&As[buf][kk][ty * 8];
            float4 ra1 = *(const float4*)&As[buf][kk][ty * 8 + 4];
            ulonglong2 rb0 = *(const ulonglong2*)&Bs[buf][kk][tx * 8];
            ulonglong2 rb1 = *(const ulonglong2*)&Bs[buf][kk][tx * 8 + 4];
            unsigned long long b2[4] = {rb0.x, rb0.y, rb1.x, rb1.y};
            float a[8] = {ra0.x, ra0.y, ra0.z, ra0.w, ra1.x, ra1.y, ra1.z, ra1.w};
#pragma unroll
            for (int i = 0; i < 8; i++) {
                unsigned long long a2;
                unsigned int au = __float_as_uint(a[i]);
                asm("mov.b64 %0, {%1, %1};" : "=l"(a2) : "r"(au));
#pragma unroll
                for (int jp = 0; jp < 4; jp++) {
                    asm("fma.rn.f32x2 %0, %1, %2, %3;"
                        : "=l"(acc2[i][jp])
                        : "l"(a2), "l"(b2[jp]), "l"(acc2[i][jp]));
                }
            }
        }
    };

    load_tile(0);
    store_tile(0);
    __syncthreads();
    int buf = 0;
    for (int k0 = 16; k0 < K; k0 += 16) {
        load_tile(k0);
        compute(buf);
        store_tile(buf ^ 1);
        __syncthreads();
        buf ^= 1;
    }
    compute(buf);

#pragma unroll
    for (int i = 0; i < 8; i++) {
        int gr = r0 + ty * 8 + i;
        if (gr < nrows) {
            float d  = g_dinv[gr];
            float of[8];
#pragma unroll
            for (int jp = 0; jp < 4; jp++) {
                unsigned int lo, hi;
                asm("mov.b64 {%0, %1}, %2;" : "=r"(lo), "=r"(hi) : "l"(acc2[i][jp]));
                of[2 * jp]     = __uint_as_float(lo) * d;
                of[2 * jp + 1] = __uint_as_float(hi) * d;
            }
            size_t base = (size_t)gr * 128 + tx * 8;
            *(float4*)(g_XW + base)     = make_float4(of[0], of[1], of[2], of[3]);
            *(float4*)(g_XW + base + 4) = make_float4(of[4], of[5], of[6], of[7]);
        }
    }
}

// ---------------- CSR aggregation: one warp per node, zero atomics ----------------
// AGG[d] = (XWs[d] + sum_{incoming} XWs[src]) * dinv[d]
// MODE 0: write g_AGG + fused BN column stats (block-reduced, atomics to g_stats[which]).
// MODE 1: head — apply bmu/bls and write split mu/logstd directly to out.
// 512 threads = 16 warps/block.
template <int MODE>
__global__ void __launch_bounds__(512) k_agg(int n, int which,
                                             const float* __restrict__ bmu,
                                             const float* __restrict__ bls,
                                             float* __restrict__ out) {
    const int gid  = blockIdx.x * blockDim.x + threadIdx.x;
    const int node = gid >> 5;
    const int lane = gid & 31;
    const bool ok  = (node < n);

    float4 o = make_float4(0.f, 0.f, 0.f, 0.f);
    if (ok) {
        const int base = __ldg(&g_rows[node]);
        const int end  = __ldg(&g_rows[node + 1]);
        const size_t loff = (size_t)lane * 4;

        float4 acc = __ldg((const float4*)(g_XW + (size_t)node * 128 + loff));  // self-loop
        float4 acc2 = make_float4(0.f, 0.f, 0.f, 0.f);

        int j = base;
        for (; j + 3 < end; j += 4) {             // 4-way unroll: MLP_eff ~4 on the gather chain
            int s0 = __ldg(&g_esrc[j]);
            int s1 = __ldg(&g_esrc[j + 1]);
            int s2 = __ldg(&g_esrc[j + 2]);
            int s3 = __ldg(&g_esrc[j + 3]);
            float4 v0 = __ldg((const float4*)(g_XW + (size_t)s0 * 128 + loff));
            float4 v1 = __ldg((const float4*)(g_XW + (size_t)s1 * 128 + loff));
            float4 v2 = __ldg((const float4*)(g_XW + (size_t)s2 * 128 + loff));
            float4 v3 = __ldg((const float4*)(g_XW + (size_t)s3 * 128 + loff));
            acc.x  += v0.x + v1.x;  acc.y  += v0.y + v1.y;
            acc.z  += v0.z + v1.z;  acc.w  += v0.w + v1.w;
            acc2.x += v2.x + v3.x;  acc2.y += v2.y + v3.y;
            acc2.z += v2.z + v3.z;  acc2.w += v2.w + v3.w;
        }
        for (; j < end; j++) {
            int s0 = __ldg(&g_esrc[j]);
            float4 v0 = __ldg((const float4*)(g_XW + (size_t)s0 * 128 + loff));
            acc.x += v0.x; acc.y += v0.y; acc.z += v0.z; acc.w += v0.w;
        }
        acc.x += acc2.x; acc.y += acc2.y; acc.z += acc2.z; acc.w += acc2.w;

        float w = __ldg(&g_dinv[node]);
        o = make_float4(acc.x * w, acc.y * w, acc.z * w, acc.w * w);

        if (MODE == 0) {
            *(float4*)(g_AGG + (size_t)node * 128 + (size_t)lane * 4) = o;
        } else {
            if (lane < 16) {
                int c = lane * 4;
                float4 r = make_float4(o.x + bmu[c], o.y + bmu[c + 1],
                                       o.z + bmu[c + 2], o.w + bmu[c + 3]);
                *(float4*)(out + (size_t)node * 64 + c) = r;
            } else {
                int c = (lane - 16) * 4;
                float4 r = make_float4(o.x + bls[c], o.y + bls[c + 1],
                                       o.z + bls[c + 2], o.w + bls[c + 3]);
                *(float4*)(out + (size_t)n * 64 + (size_t)node * 64 + c) = r;
            }
        }
    }

    if (MODE == 0) {
        // fused BN stats: block-reduce 16 warps' rows, then 256 atomics to g_stats[which].
        // Tail warps (node >= n) contribute zeros (stats-neutral). No early returns above.
        __shared__ float ssum[16][128];
        __shared__ float ssq [16][128];
        const int w16 = threadIdx.x >> 5;
        *(float4*)&ssum[w16][lane * 4] = o;
        float4 q = make_float4(o.x * o.x, o.y * o.y, o.z * o.z, o.w * o.w);
        *(float4*)&ssq[w16][lane * 4] = q;
        __syncthreads();

        if (w16 == 0) {
#pragma unroll
            for (int j = 0; j < 4; j++) {
                int c = lane * 4 + j;
                float s = 0.f, sq = 0.f;
#pragma unroll
                for (int r = 0; r < 16; r++) { s += ssum[r][c]; sq += ssq[r][c]; }
                atomicAdd(&g_stats[which][c],       s);
                atomicAdd(&g_stats[which][128 + c], sq);
            }
        }
    }
}

__global__ void k_coef(int which, const float* __restrict__ g,
                       const float* __restrict__ bt, float invn) {
    int c = threadIdx.x;  // 128 threads
    float m  = g_stats[which][c] * invn;
    float vv = g_stats[which][128 + c] * invn - m * m;
    float sc = g[c] * rsqrtf(vv + EPSV);
    g_coef[which][c]       = sc;
    g_coef[which][128 + c] = bt[c] - m * sc;   // conv bias cancels under BN mean-subtraction
}

// ---------------- launch ----------------
extern "C" void kernel_launch(void* const* d_in, const int* in_sizes, int n_in,
                              void* d_out, int out_size) {
    const float* x   = (const float*)d_in[0];
    const float* W1  = (const float*)d_in[1];
    const float* g1  = (const float*)d_in[3];
    const float* bt1 = (const float*)d_in[4];
    const float* W2  = (const float*)d_in[5];
    const float* g2  = (const float*)d_in[7];
    const float* bt2 = (const float*)d_in[8];
    const float* Wmu = (const float*)d_in[9];
    const float* bmu = (const float*)d_in[10];
    const float* Wls = (const float*)d_in[11];
    const float* bls = (const float*)d_in[12];
    const int*   ei  = (const int*)d_in[13];
    float* out = (float*)d_out;

    const int n = in_sizes[0] / INF;      // 100000
    const int e = in_sizes[13] / 2;       // 1600000
    const int* src = ei;
    const int* dst = ei + e;

    const int TB = 256;
    const int nb_n    = (n + TB - 1) / TB;            // 391
    const int nb_e    = (e + TB - 1) / TB;
    const int nb_agg  = (n * 32 + 511) / 512;         // 16 warps/block, 1 warp/node
    const int nb_gemm = (n + 127) / 128;
    const float invn = 1.0f / (float)n;

    // degree histogram -> CSR by dst (rebuilt every replay; deterministic)
    k_init<<<nb_n, TB>>>(n);
    k_deg<<<nb_e, TB>>>(dst, e);
    k_scan_a<<<nb_n, TB>>>(n);
    k_scan_b<<<1, 512>>>(nb_n, n, e);
    k_scan_c<<<nb_n, TB>>>(n);
    k_reorder<<<nb_e, TB>>>(src, dst, e);

    // ---- layer 1: conv(x,W1) -> CSR aggregate [stats fused] -> BN coefs ----
    k_gemm<INF, false><<<nb_gemm, TB>>>(x, W1, W1, 128, 0, n);
    k_agg<0><<<nb_agg, 512>>>(n, 0, nullptr, nullptr, nullptr);
    k_coef<<<1, 128>>>(0, g1, bt1, invn);

    // ---- layer 2: conv(relu(bn(AGG)),W2) [BN fused into A-load] ----
    k_gemm<HID, true><<<nb_gemm, TB>>>(nullptr, W2, W2, 128, 0, n);
    k_agg<0><<<nb_agg, 512>>>(n, 1, nullptr, nullptr, nullptr);
    k_coef<<<1, 128>>>(1, g2, bt2, invn);

    // ---- heads: conv(relu(bn(AGG)), [Wmu|Wls]) -> aggregate + biases -> out ----
    k_gemm<HID, true><<<nb_gemm, TB>>>(nullptr, Wmu, Wls, OUTF, 1, n);
    k_agg<1><<<nb_agg, 512>>>(n, 0, bmu, bls, out);
}